// round 8
// baseline (speedup 1.0000x reference)
#include <cuda_runtime.h>
#include <math.h>

#define BB 64
#define CIN 256
#define COUT 256
#define HH 64
#define WW 64
#define NB 8
#define HID 128
#define HWPIX 4096

#define TILE_H 8
#define CONV_THREADS 128
#define CHALF 128                 /* channels per filter-smem pass */
#define XT_ROWS 10                /* TILE_H + 2 halo */
#define XT_LCOLS 66               /* logical cols (64 + 2 halo) */
#define XT_STRIDE 69              /* padded stride in float2 units */
#define XT_ELEMS (XT_ROWS * XT_LCOLS)   /* 660 */
#define NLD 6
#define FS2_ELEMS (CHALF * 9 * 4) /* 4608 float2 = 36 KB */

// -------- scratch (no cudaMalloc allowed) --------
__device__ __align__(16) float g_pooled[BB * CIN];
__device__ __align__(16) float g_mix[BB * COUT * NB];
__device__ __align__(16) float g_y[(size_t)BB * NB * HWPIX];

// -------- packed f32x2 helpers (sm_103a) --------
static __device__ __forceinline__ unsigned long long pk2(float lo, float hi) {
    unsigned long long r;
    asm("mov.b64 %0, {%1, %2};" : "=l"(r) : "f"(lo), "f"(hi));
    return r;
}
static __device__ __forceinline__ void upk2(unsigned long long v, float &lo, float &hi) {
    asm("mov.b64 {%0, %1}, %2;" : "=f"(lo), "=f"(hi) : "l"(v));
}
static __device__ __forceinline__ unsigned long long fma2(
    unsigned long long a, unsigned long long b, unsigned long long c) {
    unsigned long long d;
    asm("fma.rn.f32x2 %0, %1, %2, %3;" : "=l"(d) : "l"(a), "l"(b), "l"(c));
    return d;
}
static __device__ __forceinline__ unsigned long long lds64(const float2* p) {
    unsigned long long r;
    asm("ld.shared.b64 %0, [%1];" : "=l"(r) : "l"((unsigned long long)__cvta_generic_to_shared(p)));
    return r;
}

// -------- kernel 1: zero g_pooled --------
__global__ void zero_kernel() {
    int i = blockIdx.x * blockDim.x + threadIdx.x;
    if (i < (BB * CIN) / 4) ((float4*)g_pooled)[i] = make_float4(0.f, 0.f, 0.f, 0.f);
}

// -------- kernel 2: fused 3x3 conv (8 filters, all 256 ch) + pool partials --------
// Grid: 64 b * 8 htiles = 512 CTAs, 128 threads.
// Thread t: output row r = t>>4, pixels p_j = (t&15) + 16*j, j=0..3 (STRIDED -> all
// x-tile LDS.64 are lane-stride-1 float2 = conflict-free).
// fma2 pairs two FILTERS (2np, 2np+1); x stored duplicated (v,v) in smem.
__global__ __launch_bounds__(CONV_THREADS, 4)
void conv_pool_kernel(const float* __restrict__ x, const float* __restrict__ bf) {
    __shared__ float2 fs2[FS2_ELEMS];                 // [(cl*9+tap)*4+np]
    __shared__ float2 xd[2][XT_ROWS * XT_STRIDE];     // duplicated x tile, dbl-buffered

    const int t  = threadIdx.x;
    const int ht = blockIdx.x & 7;
    const int b  = blockIdx.x >> 3;
    const int h0 = ht * TILE_H;
    const int r  = t >> 4;
    const int wl = t & 15;

    // per-thread load slots for the 660-elem logical tile
    int  offk[NLD], sidx[NLD];
    bool vk[NLD], pmk[NLD], ik[NLD];
#pragma unroll
    for (int k = 0; k < NLD; k++) {
        int idx = t + k * CONV_THREADS;
        vk[k] = false; pmk[k] = false; ik[k] = false; offk[k] = 0; sidx[k] = 0;
        if (idx < XT_ELEMS) {
            ik[k] = true;
            int row = idx / XT_LCOLS, col = idx % XT_LCOLS;
            sidx[k] = row * XT_STRIDE + col;
            int gh = h0 - 1 + row, gw = col - 1;
            if (gh >= 0 && gh < HH && gw >= 0 && gw < WW) {
                vk[k]  = true;
                offk[k] = gh * WW + gw;
                pmk[k] = (row >= 1 && row <= TILE_H && col >= 1 && col <= WW);
            }
        }
    }
    const float* xb = x + (size_t)b * CIN * HWPIX;

    // prefetch channel 0
    float ld[NLD];
#pragma unroll
    for (int k = 0; k < NLD; k++) ld[k] = vk[k] ? __ldg(xb + offk[k]) : 0.f;

    unsigned long long acc[4][4];    // [np = filter-pair][j = strided pixel]
#pragma unroll
    for (int np = 0; np < 4; np++)
#pragma unroll
        for (int j = 0; j < 4; j++) acc[np][j] = 0ULL;

    for (int c = 0; c < CIN; c++) {
        const int buf = c & 1;
        const int cl  = c & (CHALF - 1);

        // stage filters for this 128-channel half
        if (cl == 0) {
            if (c != 0) __syncthreads();   // prior compute must finish reading fs2
            for (int i = t; i < FS2_ELEMS; i += CONV_THREADS) {
                int fcl = i / 36, rem = i % 36, tap = rem / 4, np = rem % 4;
                int gidx = (c + fcl) * 9 + tap;
                fs2[i] = make_float2(bf[(2 * np) * 2304 + gidx],
                                     bf[(2 * np + 1) * 2304 + gidx]);
            }
        }

        // store duplicated x tile + pool partial from registers
        float ps = 0.f;
#pragma unroll
        for (int k = 0; k < NLD; k++) {
            if (ik[k]) xd[buf][sidx[k]] = make_float2(ld[k], ld[k]);
            if (pmk[k]) ps += ld[k];
        }
        __syncthreads();   // tile (and filters on reload iters) ready

        // pool partial (one atomic per warp per channel)
#pragma unroll
        for (int o = 16; o > 0; o >>= 1) ps += __shfl_down_sync(0xffffffffu, ps, o);
        if ((t & 31) == 0) atomicAdd(&g_pooled[b * CIN + c], ps);

        // prefetch next channel
        if (c + 1 < CIN) {
            const float* xc = xb + (size_t)(c + 1) * HWPIX;
#pragma unroll
            for (int k = 0; k < NLD; k++) ld[k] = vk[k] ? __ldg(xc + offk[k]) : 0.f;
        }

        // compute: per dy: 12 conflict-free x LDS.64 + 3 dx * (4 f LDS.64 + 16 fma2)
        const float2* fc = fs2 + cl * 36;
        const float2* xt = xd[buf] + 1 + wl;   // logical col of pixel wl
#pragma unroll
        for (int dy = 0; dy < 3; dy++) {
            const float2* xrow = xt + (r + dy) * XT_STRIDE;
            unsigned long long xv[4][3];
#pragma unroll
            for (int j = 0; j < 4; j++)
#pragma unroll
                for (int dx = 0; dx < 3; dx++)
                    xv[j][dx] = lds64(xrow + 16 * j + dx - 1);
#pragma unroll
            for (int dx = 0; dx < 3; dx++) {
                const float2* fp = fc + (dy * 3 + dx) * 4;
                unsigned long long f0  = lds64(fp + 0);
                unsigned long long f1  = lds64(fp + 1);
                unsigned long long f2v = lds64(fp + 2);
                unsigned long long f3  = lds64(fp + 3);
#pragma unroll
                for (int j = 0; j < 4; j++) {
                    unsigned long long xvv = xv[j][dx];
                    acc[0][j] = fma2(xvv, f0,  acc[0][j]);
                    acc[1][j] = fma2(xvv, f1,  acc[1][j]);
                    acc[2][j] = fma2(xvv, f2v, acc[2][j]);
                    acc[3][j] = fma2(xvv, f3,  acc[3][j]);
                }
            }
        }
    }

    // stores: y[b, n, h, wl + 16j]; lanes are stride-1 -> coalesced 64B segments
    const int h = h0 + r;
#pragma unroll
    for (int np = 0; np < 4; np++) {
        float* y0 = g_y + ((size_t)(b * NB + 2 * np) * HWPIX) + h * WW + wl;
        float* y1 = y0 + HWPIX;
#pragma unroll
        for (int j = 0; j < 4; j++) {
            float lo, hi;
            upk2(acc[np][j], lo, hi);
            y0[16 * j] = lo;
            y1[16 * j] = hi;
        }
    }
}

// -------- kernel 3: attention MLP + softmax -> mix[b, o, n] --------
__global__ __launch_bounds__(COUT)
void mlp_kernel(const float* __restrict__ w1, const float* __restrict__ b1,
                const float* __restrict__ w2, const float* __restrict__ b2) {
    __shared__ float psm[CIN];
    __shared__ float hs[HID];
    const int b = blockIdx.x, t = threadIdx.x;

    psm[t] = g_pooled[b * CIN + t] * (1.f / (float)HWPIX);
    __syncthreads();

    if (t < HID) {
        float a = b1[t];
        const float* wr = w1 + t * CIN;
        for (int c = 0; c < CIN; c++) a = fmaf(psm[c], wr[c], a);
        hs[t] = fmaxf(a, 0.f);
    }
    __syncthreads();

    float v[NB];
#pragma unroll
    for (int n = 0; n < NB; n++) v[n] = b2[t * NB + n];
    const float* w2b = w2 + (size_t)t * NB * HID;
    for (int k = 0; k < HID; k++) {
        float h = hs[k];
#pragma unroll
        for (int n = 0; n < NB; n++) v[n] = fmaf(h, w2b[n * HID + k], v[n]);
    }
    float m = v[0];
#pragma unroll
    for (int n = 1; n < NB; n++) m = fmaxf(m, v[n]);
    float e[NB], s = 0.f;
#pragma unroll
    for (int n = 0; n < NB; n++) { e[n] = expf(v[n] - m); s += e[n]; }
    float inv = 1.f / s;
#pragma unroll
    for (int n = 0; n < NB; n++) g_mix[b * COUT * NB + t * NB + n] = e[n] * inv;
}

// -------- kernel 4: out[b,o,p] = sum_n mix[b,o,n] * y[b,n,p] --------
// Grid: 64 b * 2 o-halves * 4 pixel-chunks = 512 CTAs, 256 threads, 4 px/thread.
// Streaming (evict-first) stores: output is never re-read.
__global__ __launch_bounds__(256)
void apply_kernel(float* __restrict__ out) {
    __shared__ __align__(16) float ms[128 * NB];
    const int b    = blockIdx.x >> 3;
    const int half = (blockIdx.x >> 2) & 1;
    const int t    = threadIdx.x;
    const int p0   = (blockIdx.x & 3) * 1024 + t * 4;

    for (int i = t; i < 128 * NB; i += 256)
        ms[i] = g_mix[b * COUT * NB + half * 128 * NB + i];
    __syncthreads();

    unsigned long long y2[NB][2];
#pragma unroll
    for (int n = 0; n < NB; n++) {
        float4 v = *(const float4*)(g_y + (size_t)(b * NB + n) * HWPIX + p0);
        y2[n][0] = pk2(v.x, v.y);
        y2[n][1] = pk2(v.z, v.w);
    }

    float* ob = out + ((size_t)b * COUT + half * 128) * HWPIX + p0;
    for (int o = 0; o < 128; o++) {
        const float4 m0 = *(const float4*)(ms + o * NB);
        const float4 m1 = *(const float4*)(ms + o * NB + 4);
        float mv[8] = {m0.x, m0.y, m0.z, m0.w, m1.x, m1.y, m1.z, m1.w};
        unsigned long long a0 = 0ULL, a1 = 0ULL;
#pragma unroll
        for (int n = 0; n < NB; n++) {
            unsigned long long fb = pk2(mv[n], mv[n]);
            a0 = fma2(y2[n][0], fb, a0);
            a1 = fma2(y2[n][1], fb, a1);
        }
        float o0, o1, o2, o3;
        upk2(a0, o0, o1);
        upk2(a1, o2, o3);
        __stcs((float4*)(ob + (size_t)o * HWPIX), make_float4(o0, o1, o2, o3));
    }
}

extern "C" void kernel_launch(void* const* d_in, const int* in_sizes, int n_in,
                              void* d_out, int out_size) {
    const float* x  = (const float*)d_in[0];
    const float* w1 = (const float*)d_in[1];
    const float* b1 = (const float*)d_in[2];
    const float* w2 = (const float*)d_in[3];
    const float* b2 = (const float*)d_in[4];
    const float* bf = (const float*)d_in[5];
    float* out = (float*)d_out;

    zero_kernel<<<(BB * CIN / 4 + 255) / 256, 256>>>();
    conv_pool_kernel<<<BB * 8, CONV_THREADS>>>(x, bf);
    mlp_kernel<<<BB, COUT>>>(w1, b1, w2, b2);
    apply_kernel<<<BB * 8, 256>>>(out);
}

// round 9
// speedup vs baseline: 1.0047x; 1.0047x over previous
#include <cuda_runtime.h>
#include <math.h>

#define BB 64
#define CIN 256
#define COUT 256
#define HH 64
#define WW 64
#define NB 8
#define HID 128
#define HWPIX 4096

#define TILE_H 8
#define CONV_THREADS 128
#define CHALF 128                 /* channels per filter-smem pass */
#define XT_ROWS 10                /* TILE_H + 2 halo */
#define XT_LCOLS 66               /* logical cols (64 + 2 halo) */
#define XT_STRIDE 69              /* padded stride in float2 units */
#define XT_ELEMS (XT_ROWS * XT_LCOLS)   /* 660 */
#define NLD 6
#define FS2_ELEMS (CHALF * 9 * 4) /* 4608 float2 = 36 KB */

// -------- scratch (no cudaMalloc allowed) --------
__device__ __align__(16) float g_pooled[BB * CIN];
__device__ __align__(16) float g_mix[BB * COUT * NB];
__device__ __align__(16) float g_y[(size_t)BB * NB * HWPIX];

// -------- packed f32x2 helpers (sm_103a) --------
static __device__ __forceinline__ unsigned long long pk2(float lo, float hi) {
    unsigned long long r;
    asm("mov.b64 %0, {%1, %2};" : "=l"(r) : "f"(lo), "f"(hi));
    return r;
}
static __device__ __forceinline__ void upk2(unsigned long long v, float &lo, float &hi) {
    asm("mov.b64 {%0, %1}, %2;" : "=f"(lo), "=f"(hi) : "l"(v));
}
static __device__ __forceinline__ unsigned long long fma2(
    unsigned long long a, unsigned long long b, unsigned long long c) {
    unsigned long long d;
    asm("fma.rn.f32x2 %0, %1, %2, %3;" : "=l"(d) : "l"(a), "l"(b), "l"(c));
    return d;
}
static __device__ __forceinline__ unsigned long long lds64(const float2* p) {
    unsigned long long r;
    asm("ld.shared.b64 %0, [%1];" : "=l"(r) : "l"((unsigned long long)__cvta_generic_to_shared(p)));
    return r;
}

// -------- kernel 1: zero g_pooled --------
__global__ void zero_kernel() {
    int i = blockIdx.x * blockDim.x + threadIdx.x;
    if (i < (BB * CIN) / 4) ((float4*)g_pooled)[i] = make_float4(0.f, 0.f, 0.f, 0.f);
}

// -------- kernel 2: fused 3x3 conv (8 filters, all 256 ch) + pool partials --------
// Grid: 64 b * 8 htiles = 512 CTAs, 128 threads.
// Thread t: output row r = t>>4, pixels p_j = (t&15) + 16*j, j=0..3 (STRIDED -> all
// x-tile LDS.64 are lane-stride-1 float2 = conflict-free).
// fma2 pairs two FILTERS (2np, 2np+1); x stored duplicated (v,v) in smem.
__global__ __launch_bounds__(CONV_THREADS, 4)
void conv_pool_kernel(const float* __restrict__ x, const float* __restrict__ bf) {
    __shared__ float2 fs2[FS2_ELEMS];                 // [(cl*9+tap)*4+np]
    __shared__ float2 xd[2][XT_ROWS * XT_STRIDE];     // duplicated x tile, dbl-buffered

    const int t  = threadIdx.x;
    const int ht = blockIdx.x & 7;
    const int b  = blockIdx.x >> 3;
    const int h0 = ht * TILE_H;
    const int r  = t >> 4;
    const int wl = t & 15;

    // per-thread load slots for the 660-elem logical tile
    int  offk[NLD], sidx[NLD];
    bool vk[NLD], pmk[NLD], ik[NLD];
#pragma unroll
    for (int k = 0; k < NLD; k++) {
        int idx = t + k * CONV_THREADS;
        vk[k] = false; pmk[k] = false; ik[k] = false; offk[k] = 0; sidx[k] = 0;
        if (idx < XT_ELEMS) {
            ik[k] = true;
            int row = idx / XT_LCOLS, col = idx % XT_LCOLS;
            sidx[k] = row * XT_STRIDE + col;
            int gh = h0 - 1 + row, gw = col - 1;
            if (gh >= 0 && gh < HH && gw >= 0 && gw < WW) {
                vk[k]  = true;
                offk[k] = gh * WW + gw;
                pmk[k] = (row >= 1 && row <= TILE_H && col >= 1 && col <= WW);
            }
        }
    }
    const float* xb = x + (size_t)b * CIN * HWPIX;

    // prefetch channel 0
    float ld[NLD];
#pragma unroll
    for (int k = 0; k < NLD; k++) ld[k] = vk[k] ? __ldg(xb + offk[k]) : 0.f;

    unsigned long long acc[4][4];    // [np = filter-pair][j = strided pixel]
#pragma unroll
    for (int np = 0; np < 4; np++)
#pragma unroll
        for (int j = 0; j < 4; j++) acc[np][j] = 0ULL;

    for (int c = 0; c < CIN; c++) {
        const int buf = c & 1;
        const int cl  = c & (CHALF - 1);

        // stage filters for this 128-channel half
        if (cl == 0) {
            if (c != 0) __syncthreads();   // prior compute must finish reading fs2
            for (int i = t; i < FS2_ELEMS; i += CONV_THREADS) {
                int fcl = i / 36, rem = i % 36, tap = rem / 4, np = rem % 4;
                int gidx = (c + fcl) * 9 + tap;
                fs2[i] = make_float2(bf[(2 * np) * 2304 + gidx],
                                     bf[(2 * np + 1) * 2304 + gidx]);
            }
        }

        // store duplicated x tile + pool partial from registers
        float ps = 0.f;
#pragma unroll
        for (int k = 0; k < NLD; k++) {
            if (ik[k]) xd[buf][sidx[k]] = make_float2(ld[k], ld[k]);
            if (pmk[k]) ps += ld[k];
        }
        __syncthreads();   // tile (and filters on reload iters) ready

        // pool partial (one atomic per warp per channel)
#pragma unroll
        for (int o = 16; o > 0; o >>= 1) ps += __shfl_down_sync(0xffffffffu, ps, o);
        if ((t & 31) == 0) atomicAdd(&g_pooled[b * CIN + c], ps);

        // prefetch next channel
        if (c + 1 < CIN) {
            const float* xc = xb + (size_t)(c + 1) * HWPIX;
#pragma unroll
            for (int k = 0; k < NLD; k++) ld[k] = vk[k] ? __ldg(xc + offk[k]) : 0.f;
        }

        // compute: per dy: 12 conflict-free x LDS.64 + 3 dx * (4 f LDS.64 + 16 fma2)
        const float2* fc = fs2 + cl * 36;
        const float2* xt = xd[buf] + 1 + wl;   // logical col of pixel wl
#pragma unroll
        for (int dy = 0; dy < 3; dy++) {
            const float2* xrow = xt + (r + dy) * XT_STRIDE;
            unsigned long long xv[4][3];
#pragma unroll
            for (int j = 0; j < 4; j++)
#pragma unroll
                for (int dx = 0; dx < 3; dx++)
                    xv[j][dx] = lds64(xrow + 16 * j + dx - 1);
#pragma unroll
            for (int dx = 0; dx < 3; dx++) {
                const float2* fp = fc + (dy * 3 + dx) * 4;
                unsigned long long f0  = lds64(fp + 0);
                unsigned long long f1  = lds64(fp + 1);
                unsigned long long f2v = lds64(fp + 2);
                unsigned long long f3  = lds64(fp + 3);
#pragma unroll
                for (int j = 0; j < 4; j++) {
                    unsigned long long xvv = xv[j][dx];
                    acc[0][j] = fma2(xvv, f0,  acc[0][j]);
                    acc[1][j] = fma2(xvv, f1,  acc[1][j]);
                    acc[2][j] = fma2(xvv, f2v, acc[2][j]);
                    acc[3][j] = fma2(xvv, f3,  acc[3][j]);
                }
            }
        }
    }

    // stores: y[b, n, h, wl + 16j]; lanes are stride-1 -> coalesced 64B segments
    const int h = h0 + r;
#pragma unroll
    for (int np = 0; np < 4; np++) {
        float* y0 = g_y + ((size_t)(b * NB + 2 * np) * HWPIX) + h * WW + wl;
        float* y1 = y0 + HWPIX;
#pragma unroll
        for (int j = 0; j < 4; j++) {
            float lo, hi;
            upk2(acc[np][j], lo, hi);
            y0[16 * j] = lo;
            y1[16 * j] = hi;
        }
    }
}

// -------- kernel 3: attention MLP + softmax -> mix[b, o, n] --------
__global__ __launch_bounds__(COUT)
void mlp_kernel(const float* __restrict__ w1, const float* __restrict__ b1,
                const float* __restrict__ w2, const float* __restrict__ b2) {
    __shared__ float psm[CIN];
    __shared__ float hs[HID];
    const int b = blockIdx.x, t = threadIdx.x;

    psm[t] = g_pooled[b * CIN + t] * (1.f / (float)HWPIX);
    __syncthreads();

    if (t < HID) {
        float a = b1[t];
        const float* wr = w1 + t * CIN;
        for (int c = 0; c < CIN; c++) a = fmaf(psm[c], wr[c], a);
        hs[t] = fmaxf(a, 0.f);
    }
    __syncthreads();

    float v[NB];
#pragma unroll
    for (int n = 0; n < NB; n++) v[n] = b2[t * NB + n];
    const float* w2b = w2 + (size_t)t * NB * HID;
    for (int k = 0; k < HID; k++) {
        float h = hs[k];
#pragma unroll
        for (int n = 0; n < NB; n++) v[n] = fmaf(h, w2b[n * HID + k], v[n]);
    }
    float m = v[0];
#pragma unroll
    for (int n = 1; n < NB; n++) m = fmaxf(m, v[n]);
    float e[NB], s = 0.f;
#pragma unroll
    for (int n = 0; n < NB; n++) { e[n] = expf(v[n] - m); s += e[n]; }
    float inv = 1.f / s;
#pragma unroll
    for (int n = 0; n < NB; n++) g_mix[b * COUT * NB + t * NB + n] = e[n] * inv;
}

// -------- kernel 4: out[b,o,p] = sum_n mix[b,o,n] * y[b,n,p] --------
// Grid: 64 b * 2 o-halves * 4 pixel-chunks = 512 CTAs, 256 threads, 4 px/thread.
// Streaming (evict-first) stores: output is never re-read.
__global__ __launch_bounds__(256)
void apply_kernel(float* __restrict__ out) {
    __shared__ __align__(16) float ms[128 * NB];
    const int b    = blockIdx.x >> 3;
    const int half = (blockIdx.x >> 2) & 1;
    const int t    = threadIdx.x;
    const int p0   = (blockIdx.x & 3) * 1024 + t * 4;

    for (int i = t; i < 128 * NB; i += 256)
        ms[i] = g_mix[b * COUT * NB + half * 128 * NB + i];
    __syncthreads();

    unsigned long long y2[NB][2];
#pragma unroll
    for (int n = 0; n < NB; n++) {
        float4 v = *(const float4*)(g_y + (size_t)(b * NB + n) * HWPIX + p0);
        y2[n][0] = pk2(v.x, v.y);
        y2[n][1] = pk2(v.z, v.w);
    }

    float* ob = out + ((size_t)b * COUT + half * 128) * HWPIX + p0;
    for (int o = 0; o < 128; o++) {
        const float4 m0 = *(const float4*)(ms + o * NB);
        const float4 m1 = *(const float4*)(ms + o * NB + 4);
        float mv[8] = {m0.x, m0.y, m0.z, m0.w, m1.x, m1.y, m1.z, m1.w};
        unsigned long long a0 = 0ULL, a1 = 0ULL;
#pragma unroll
        for (int n = 0; n < NB; n++) {
            unsigned long long fb = pk2(mv[n], mv[n]);
            a0 = fma2(y2[n][0], fb, a0);
            a1 = fma2(y2[n][1], fb, a1);
        }
        float o0, o1, o2, o3;
        upk2(a0, o0, o1);
        upk2(a1, o2, o3);
        __stcs((float4*)(ob + (size_t)o * HWPIX), make_float4(o0, o1, o2, o3));
    }
}

extern "C" void kernel_launch(void* const* d_in, const int* in_sizes, int n_in,
                              void* d_out, int out_size) {
    const float* x  = (const float*)d_in[0];
    const float* w1 = (const float*)d_in[1];
    const float* b1 = (const float*)d_in[2];
    const float* w2 = (const float*)d_in[3];
    const float* b2 = (const float*)d_in[4];
    const float* bf = (const float*)d_in[5];
    float* out = (float*)d_out;

    zero_kernel<<<(BB * CIN / 4 + 255) / 256, 256>>>();
    conv_pool_kernel<<<BB * 8, CONV_THREADS>>>(x, bf);
    mlp_kernel<<<BB, COUT>>>(w1, b1, w2, b2);
    apply_kernel<<<BB * 8, 256>>>(out);
}

// round 10
// speedup vs baseline: 1.0050x; 1.0003x over previous
#include <cuda_runtime.h>
#include <math.h>

#define BB 64
#define CIN 256
#define COUT 256
#define HH 64
#define WW 64
#define NB 8
#define HID 128
#define HWPIX 4096

#define TILE_H 8
#define CONV_THREADS 128
#define CHALF 128                 /* channels per filter-smem pass */
#define XT_ROWS 10                /* TILE_H + 2 halo */
#define XT_LCOLS 66               /* logical cols (64 + 2 halo) */
#define XT_STRIDE 69              /* padded stride in float2 units */
#define XT_ELEMS (XT_ROWS * XT_LCOLS)   /* 660 */
#define NLD 6
#define FS2_ELEMS (CHALF * 9 * 4) /* 4608 float2 = 36 KB */

// -------- scratch (no cudaMalloc allowed) --------
__device__ __align__(16) float g_pooled[BB * CIN];
__device__ __align__(16) float g_mix[BB * COUT * NB];
__device__ __align__(16) float g_y[(size_t)BB * NB * HWPIX];

// -------- packed f32x2 helpers (sm_103a) --------
static __device__ __forceinline__ unsigned long long pk2(float lo, float hi) {
    unsigned long long r;
    asm("mov.b64 %0, {%1, %2};" : "=l"(r) : "f"(lo), "f"(hi));
    return r;
}
static __device__ __forceinline__ void upk2(unsigned long long v, float &lo, float &hi) {
    asm("mov.b64 {%0, %1}, %2;" : "=f"(lo), "=f"(hi) : "l"(v));
}
static __device__ __forceinline__ unsigned long long fma2(
    unsigned long long a, unsigned long long b, unsigned long long c) {
    unsigned long long d;
    asm("fma.rn.f32x2 %0, %1, %2, %3;" : "=l"(d) : "l"(a), "l"(b), "l"(c));
    return d;
}
static __device__ __forceinline__ unsigned long long lds64(const float2* p) {
    unsigned long long r;
    asm("ld.shared.b64 %0, [%1];" : "=l"(r) : "l"((unsigned long long)__cvta_generic_to_shared(p)));
    return r;
}

// -------- kernel 1: zero g_pooled --------
__global__ void zero_kernel() {
    int i = blockIdx.x * blockDim.x + threadIdx.x;
    if (i < (BB * CIN) / 4) ((float4*)g_pooled)[i] = make_float4(0.f, 0.f, 0.f, 0.f);
}

// -------- kernel 2: fused 3x3 conv (8 filters, all 256 ch) + pool partials --------
// Grid: 64 b * 8 htiles = 512 CTAs, 128 threads.
// Thread t: output row r = t>>4, pixels p_j = (t&15) + 16*j, j=0..3 (STRIDED -> all
// x-tile LDS.64 are lane-stride-1 float2 = conflict-free).
// fma2 pairs two FILTERS (2np, 2np+1); x stored duplicated (v,v) in smem.
__global__ __launch_bounds__(CONV_THREADS, 4)
void conv_pool_kernel(const float* __restrict__ x, const float* __restrict__ bf) {
    __shared__ float2 fs2[FS2_ELEMS];                 // [(cl*9+tap)*4+np]
    __shared__ float2 xd[2][XT_ROWS * XT_STRIDE];     // duplicated x tile, dbl-buffered

    const int t  = threadIdx.x;
    const int ht = blockIdx.x & 7;
    const int b  = blockIdx.x >> 3;
    const int h0 = ht * TILE_H;
    const int r  = t >> 4;
    const int wl = t & 15;

    // per-thread load slots for the 660-elem logical tile
    int  offk[NLD], sidx[NLD];
    bool vk[NLD], pmk[NLD], ik[NLD];
#pragma unroll
    for (int k = 0; k < NLD; k++) {
        int idx = t + k * CONV_THREADS;
        vk[k] = false; pmk[k] = false; ik[k] = false; offk[k] = 0; sidx[k] = 0;
        if (idx < XT_ELEMS) {
            ik[k] = true;
            int row = idx / XT_LCOLS, col = idx % XT_LCOLS;
            sidx[k] = row * XT_STRIDE + col;
            int gh = h0 - 1 + row, gw = col - 1;
            if (gh >= 0 && gh < HH && gw >= 0 && gw < WW) {
                vk[k]  = true;
                offk[k] = gh * WW + gw;
                pmk[k] = (row >= 1 && row <= TILE_H && col >= 1 && col <= WW);
            }
        }
    }
    const float* xb = x + (size_t)b * CIN * HWPIX;

    // prefetch channel 0
    float ld[NLD];
#pragma unroll
    for (int k = 0; k < NLD; k++) ld[k] = vk[k] ? __ldg(xb + offk[k]) : 0.f;

    unsigned long long acc[4][4];    // [np = filter-pair][j = strided pixel]
#pragma unroll
    for (int np = 0; np < 4; np++)
#pragma unroll
        for (int j = 0; j < 4; j++) acc[np][j] = 0ULL;

    for (int c = 0; c < CIN; c++) {
        const int buf = c & 1;
        const int cl  = c & (CHALF - 1);

        // stage filters for this 128-channel half
        if (cl == 0) {
            if (c != 0) __syncthreads();   // prior compute must finish reading fs2
            for (int i = t; i < FS2_ELEMS; i += CONV_THREADS) {
                int fcl = i / 36, rem = i % 36, tap = rem / 4, np = rem % 4;
                int gidx = (c + fcl) * 9 + tap;
                fs2[i] = make_float2(bf[(2 * np) * 2304 + gidx],
                                     bf[(2 * np + 1) * 2304 + gidx]);
            }
        }

        // store duplicated x tile + pool partial from registers
        float ps = 0.f;
#pragma unroll
        for (int k = 0; k < NLD; k++) {
            if (ik[k]) xd[buf][sidx[k]] = make_float2(ld[k], ld[k]);
            if (pmk[k]) ps += ld[k];
        }
        __syncthreads();   // tile (and filters on reload iters) ready

        // pool partial (one atomic per warp per channel)
#pragma unroll
        for (int o = 16; o > 0; o >>= 1) ps += __shfl_down_sync(0xffffffffu, ps, o);
        if ((t & 31) == 0) atomicAdd(&g_pooled[b * CIN + c], ps);

        // prefetch next channel
        if (c + 1 < CIN) {
            const float* xc = xb + (size_t)(c + 1) * HWPIX;
#pragma unroll
            for (int k = 0; k < NLD; k++) ld[k] = vk[k] ? __ldg(xc + offk[k]) : 0.f;
        }

        // compute: per dy: 12 conflict-free x LDS.64 + 3 dx * (4 f LDS.64 + 16 fma2)
        const float2* fc = fs2 + cl * 36;
        const float2* xt = xd[buf] + 1 + wl;   // logical col of pixel wl
#pragma unroll
        for (int dy = 0; dy < 3; dy++) {
            const float2* xrow = xt + (r + dy) * XT_STRIDE;
            unsigned long long xv[4][3];
#pragma unroll
            for (int j = 0; j < 4; j++)
#pragma unroll
                for (int dx = 0; dx < 3; dx++)
                    xv[j][dx] = lds64(xrow + 16 * j + dx - 1);
#pragma unroll
            for (int dx = 0; dx < 3; dx++) {
                const float2* fp = fc + (dy * 3 + dx) * 4;
                unsigned long long f0  = lds64(fp + 0);
                unsigned long long f1  = lds64(fp + 1);
                unsigned long long f2v = lds64(fp + 2);
                unsigned long long f3  = lds64(fp + 3);
#pragma unroll
                for (int j = 0; j < 4; j++) {
                    unsigned long long xvv = xv[j][dx];
                    acc[0][j] = fma2(xvv, f0,  acc[0][j]);
                    acc[1][j] = fma2(xvv, f1,  acc[1][j]);
                    acc[2][j] = fma2(xvv, f2v, acc[2][j]);
                    acc[3][j] = fma2(xvv, f3,  acc[3][j]);
                }
            }
        }
    }

    // stores: y[b, n, h, wl + 16j]; lanes are stride-1 -> coalesced 64B segments
    const int h = h0 + r;
#pragma unroll
    for (int np = 0; np < 4; np++) {
        float* y0 = g_y + ((size_t)(b * NB + 2 * np) * HWPIX) + h * WW + wl;
        float* y1 = y0 + HWPIX;
#pragma unroll
        for (int j = 0; j < 4; j++) {
            float lo, hi;
            upk2(acc[np][j], lo, hi);
            y0[16 * j] = lo;
            y1[16 * j] = hi;
        }
    }
}

// -------- kernel 3: attention MLP + softmax -> mix[b, o, n] --------
__global__ __launch_bounds__(COUT)
void mlp_kernel(const float* __restrict__ w1, const float* __restrict__ b1,
                const float* __restrict__ w2, const float* __restrict__ b2) {
    __shared__ float psm[CIN];
    __shared__ float hs[HID];
    const int b = blockIdx.x, t = threadIdx.x;

    psm[t] = g_pooled[b * CIN + t] * (1.f / (float)HWPIX);
    __syncthreads();

    if (t < HID) {
        float a = b1[t];
        const float* wr = w1 + t * CIN;
        for (int c = 0; c < CIN; c++) a = fmaf(psm[c], wr[c], a);
        hs[t] = fmaxf(a, 0.f);
    }
    __syncthreads();

    float v[NB];
#pragma unroll
    for (int n = 0; n < NB; n++) v[n] = b2[t * NB + n];
    const float* w2b = w2 + (size_t)t * NB * HID;
    for (int k = 0; k < HID; k++) {
        float h = hs[k];
#pragma unroll
        for (int n = 0; n < NB; n++) v[n] = fmaf(h, w2b[n * HID + k], v[n]);
    }
    float m = v[0];
#pragma unroll
    for (int n = 1; n < NB; n++) m = fmaxf(m, v[n]);
    float e[NB], s = 0.f;
#pragma unroll
    for (int n = 0; n < NB; n++) { e[n] = expf(v[n] - m); s += e[n]; }
    float inv = 1.f / s;
#pragma unroll
    for (int n = 0; n < NB; n++) g_mix[b * COUT * NB + t * NB + n] = e[n] * inv;
}

// -------- kernel 4: out[b,o,p] = sum_n mix[b,o,n] * y[b,n,p] --------
// Grid: 64 b * 2 o-halves * 4 pixel-chunks = 512 CTAs, 256 threads, 4 px/thread.
// Streaming (evict-first) stores: output is never re-read.
__global__ __launch_bounds__(256)
void apply_kernel(float* __restrict__ out) {
    __shared__ __align__(16) float ms[128 * NB];
    const int b    = blockIdx.x >> 3;
    const int half = (blockIdx.x >> 2) & 1;
    const int t    = threadIdx.x;
    const int p0   = (blockIdx.x & 3) * 1024 + t * 4;

    for (int i = t; i < 128 * NB; i += 256)
        ms[i] = g_mix[b * COUT * NB + half * 128 * NB + i];
    __syncthreads();

    unsigned long long y2[NB][2];
#pragma unroll
    for (int n = 0; n < NB; n++) {
        float4 v = *(const float4*)(g_y + (size_t)(b * NB + n) * HWPIX + p0);
        y2[n][0] = pk2(v.x, v.y);
        y2[n][1] = pk2(v.z, v.w);
    }

    float* ob = out + ((size_t)b * COUT + half * 128) * HWPIX + p0;
    for (int o = 0; o < 128; o++) {
        const float4 m0 = *(const float4*)(ms + o * NB);
        const float4 m1 = *(const float4*)(ms + o * NB + 4);
        float mv[8] = {m0.x, m0.y, m0.z, m0.w, m1.x, m1.y, m1.z, m1.w};
        unsigned long long a0 = 0ULL, a1 = 0ULL;
#pragma unroll
        for (int n = 0; n < NB; n++) {
            unsigned long long fb = pk2(mv[n], mv[n]);
            a0 = fma2(y2[n][0], fb, a0);
            a1 = fma2(y2[n][1], fb, a1);
        }
        float o0, o1, o2, o3;
        upk2(a0, o0, o1);
        upk2(a1, o2, o3);
        __stcs((float4*)(ob + (size_t)o * HWPIX), make_float4(o0, o1, o2, o3));
    }
}

extern "C" void kernel_launch(void* const* d_in, const int* in_sizes, int n_in,
                              void* d_out, int out_size) {
    const float* x  = (const float*)d_in[0];
    const float* w1 = (const float*)d_in[1];
    const float* b1 = (const float*)d_in[2];
    const float* w2 = (const float*)d_in[3];
    const float* b2 = (const float*)d_in[4];
    const float* bf = (const float*)d_in[5];
    float* out = (float*)d_out;

    zero_kernel<<<(BB * CIN / 4 + 255) / 256, 256>>>();
    conv_pool_kernel<<<BB * 8, CONV_THREADS>>>(x, bf);
    mlp_kernel<<<BB, COUT>>>(w1, b1, w2, b2);
    apply_kernel<<<BB * 8, 256>>>(out);
}

// round 11
// speedup vs baseline: 1.2251x; 1.2190x over previous
#include <cuda_runtime.h>
#include <math.h>

#define BB 64
#define CIN 256
#define COUT 256
#define HH 64
#define WW 64
#define NB 8
#define HID 128
#define HWPIX 4096

#define TILE_H 16
#define CONV_THREADS 256
#define XT_ROWS 18                /* TILE_H + 2 halo */
#define XT_COLS 66                /* 64 + 2 halo */
#define XT_ELEMS (XT_ROWS * XT_COLS)   /* 1188 */
#define NLD 5
#define NPASS_PAIRS 64            /* channel-pairs per filter-smem pass */
#define FS2_ELEMS (NPASS_PAIRS * 9 * NB)  /* 4608 float2 = 36 KB */

// -------- scratch (no cudaMalloc allowed) --------
__device__ __align__(16) float g_pooled[BB * CIN];
__device__ __align__(16) float g_mix[BB * COUT * NB];
__device__ __align__(16) float g_y[(size_t)BB * NB * HWPIX];

// -------- packed f32x2 helpers (sm_103a) --------
static __device__ __forceinline__ unsigned long long pk2(float lo, float hi) {
    unsigned long long r;
    asm("mov.b64 %0, {%1, %2};" : "=l"(r) : "f"(lo), "f"(hi));
    return r;
}
static __device__ __forceinline__ void upk2(unsigned long long v, float &lo, float &hi) {
    asm("mov.b64 {%0, %1}, %2;" : "=f"(lo), "=f"(hi) : "l"(v));
}
static __device__ __forceinline__ unsigned long long fma2(
    unsigned long long a, unsigned long long b, unsigned long long c) {
    unsigned long long d;
    asm("fma.rn.f32x2 %0, %1, %2, %3;" : "=l"(d) : "l"(a), "l"(b), "l"(c));
    return d;
}
static __device__ __forceinline__ unsigned long long lds64(const float2* p) {
    unsigned long long r;
    asm("ld.shared.b64 %0, [%1];" : "=l"(r) : "l"((unsigned long long)__cvta_generic_to_shared(p)));
    return r;
}

// -------- kernel 1: zero g_pooled --------
__global__ void zero_kernel() {
    int i = blockIdx.x * blockDim.x + threadIdx.x;
    if (i < (BB * CIN) / 4) ((float4*)g_pooled)[i] = make_float4(0.f, 0.f, 0.f, 0.f);
}

// -------- kernel 2: fused 3x3 conv (8 filters) + pool, channel-pair fma2 --------
// Grid: 64 b * 4 htiles = 256 CTAs, 256 threads (single wave at 2 CTAs/SM).
// Warp w owns output rows 2w, 2w+1; lane l owns pixels l and l+32 in each row.
// fma2 lanes = two consecutive CHANNELS: x tile stored interleaved (x_c0, x_c1),
// filters pre-paired (f_c0, f_c1)[tap][n]. Both operands: plain LDS.64, no MOVs.
__global__ __launch_bounds__(CONV_THREADS, 2)
void conv_pool_kernel(const float* __restrict__ x, const float* __restrict__ bf) {
    extern __shared__ float2 smem2[];
    float2* fs2 = smem2;                    // [pl*9+tap][n] filter pairs (36 KB)
    float2* xd[2] = { smem2 + FS2_ELEMS, smem2 + FS2_ELEMS + XT_ELEMS };

    const int t  = threadIdx.x;
    const int w  = t >> 5;
    const int l  = t & 31;
    const int b  = blockIdx.x >> 2;
    const int h0 = (blockIdx.x & 3) * TILE_H;
    const int ra = 2 * w;                    // tile-local output row pair

    // per-thread staging slots for the 1188-elem tile
    int  offk[NLD], sidx[NLD];
    bool vk[NLD], pmk[NLD], ik[NLD];
#pragma unroll
    for (int k = 0; k < NLD; k++) {
        int idx = t + k * CONV_THREADS;
        vk[k] = false; pmk[k] = false; ik[k] = false; offk[k] = 0; sidx[k] = 0;
        if (idx < XT_ELEMS) {
            ik[k] = true;
            int row = idx / XT_COLS, col = idx % XT_COLS;
            sidx[k] = idx;
            int gh = h0 - 1 + row, gw = col - 1;
            if (gh >= 0 && gh < HH && gw >= 0 && gw < WW) {
                vk[k]  = true;
                offk[k] = gh * WW + gw;
                pmk[k] = (row >= 1 && row <= TILE_H && col >= 1 && col <= WW);
            }
        }
    }
    const float* xb = x + (size_t)b * CIN * HWPIX;

    // prefetch channel pair 0 (planes 0 and 1)
    float ld0[NLD], ld1[NLD];
#pragma unroll
    for (int k = 0; k < NLD; k++) {
        ld0[k] = vk[k] ? __ldg(xb + offk[k]) : 0.f;
        ld1[k] = vk[k] ? __ldg(xb + HWPIX + offk[k]) : 0.f;
    }

    unsigned long long acc[NB][4];   // [n][rowA:l, rowA:l+32, rowB:l, rowB:l+32]
#pragma unroll
    for (int n = 0; n < NB; n++)
#pragma unroll
        for (int j = 0; j < 4; j++) acc[n][j] = 0ULL;

    for (int pr = 0; pr < CIN / 2; pr++) {          // channel pairs
        const int pl = pr & (NPASS_PAIRS - 1);

        // stage filter pairs for this 64-pair pass
        if (pl == 0) {
            if (pr != 0) __syncthreads();           // readers of old fs2 done
            const int pbase = (pr >> 6) * 2 * NPASS_PAIRS;   // first channel of pass
            for (int i = t; i < FS2_ELEMS; i += CONV_THREADS) {
                int n = i / (NPASS_PAIRS * 9), rem = i % (NPASS_PAIRS * 9);
                int fpl = rem / 9, tap = rem % 9;
                int a0 = n * 2304 + (pbase + 2 * fpl) * 9 + tap;
                fs2[(fpl * 9 + tap) * NB + n] = make_float2(bf[a0], bf[a0 + 9]);
            }
        }

        // store interleaved tile + pool partials
        float2* xt = xd[pr & 1];
        float ps0 = 0.f, ps1 = 0.f;
#pragma unroll
        for (int k = 0; k < NLD; k++) {
            if (ik[k]) xt[sidx[k]] = make_float2(ld0[k], ld1[k]);
            if (pmk[k]) { ps0 += ld0[k]; ps1 += ld1[k]; }
        }
        __syncthreads();

        // pool partials (two interleaved shuffle chains, 2 atomics per warp)
#pragma unroll
        for (int o = 16; o > 0; o >>= 1) {
            ps0 += __shfl_down_sync(0xffffffffu, ps0, o);
            ps1 += __shfl_down_sync(0xffffffffu, ps1, o);
        }
        if (l == 0) {
            atomicAdd(&g_pooled[b * CIN + 2 * pr], ps0);
            atomicAdd(&g_pooled[b * CIN + 2 * pr + 1], ps1);
        }

        // prefetch next channel pair
        if (pr + 1 < CIN / 2) {
            const float* xc = xb + (size_t)(2 * pr + 2) * HWPIX;
#pragma unroll
            for (int k = 0; k < NLD; k++) {
                ld0[k] = vk[k] ? __ldg(xc + offk[k]) : 0.f;
                ld1[k] = vk[k] ? __ldg(xc + HWPIX + offk[k]) : 0.f;
            }
        }

        // compute: per dy, 12 conflict-free x LDS.64 + 24 broadcast f LDS.64 + 96 fma2
        const float2* fc = fs2 + pl * 72;
#pragma unroll
        for (int dy = 0; dy < 3; dy++) {
            const float2* rowA = xt + (ra + dy) * XT_COLS + l;
            const float2* rowB = rowA + XT_COLS;
            unsigned long long xa[3], xah[3], xbv[3], xbh[3];
#pragma unroll
            for (int dx = 0; dx < 3; dx++) {
                xa[dx]  = lds64(rowA + dx);
                xah[dx] = lds64(rowA + 32 + dx);
                xbv[dx] = lds64(rowB + dx);
                xbh[dx] = lds64(rowB + 32 + dx);
            }
#pragma unroll
            for (int dx = 0; dx < 3; dx++) {
                const float2* fp = fc + (dy * 3 + dx) * NB;
#pragma unroll
                for (int n = 0; n < NB; n++) {
                    unsigned long long f = lds64(fp + n);
                    acc[n][0] = fma2(xa[dx],  f, acc[n][0]);
                    acc[n][1] = fma2(xah[dx], f, acc[n][1]);
                    acc[n][2] = fma2(xbv[dx], f, acc[n][2]);
                    acc[n][3] = fma2(xbh[dx], f, acc[n][3]);
                }
            }
        }
    }

    // epilogue: y = lo+hi (sum of the two channel-parity partials)
    const int h = h0 + ra;
#pragma unroll
    for (int n = 0; n < NB; n++) {
        float* yb = g_y + ((size_t)(b * NB + n) * HWPIX) + h * WW;
        float lo, hi;
        upk2(acc[n][0], lo, hi); yb[l]           = lo + hi;
        upk2(acc[n][1], lo, hi); yb[l + 32]      = lo + hi;
        upk2(acc[n][2], lo, hi); yb[WW + l]      = lo + hi;
        upk2(acc[n][3], lo, hi); yb[WW + l + 32] = lo + hi;
    }
}

// -------- kernel 3: attention MLP + softmax (warp-cooperative, coalesced) --------
__global__ __launch_bounds__(256)
void mlp_kernel(const float* __restrict__ w1, const float* __restrict__ b1,
                const float* __restrict__ w2, const float* __restrict__ b2) {
    __shared__ float psm[CIN];
    __shared__ float hs[HID];
    __shared__ float raw[COUT * NB];
    const int b = blockIdx.x, t = threadIdx.x;
    const int w = t >> 5, l = t & 31;

    psm[t] = g_pooled[b * CIN + t] * (1.f / (float)HWPIX);
    __syncthreads();

    // h = relu(w1 @ pooled + b1): warp per row group, lane covers 8 c's
#pragma unroll
    for (int i = 0; i < HID / 8; i++) {
        int j = w * (HID / 8) + i;
        float4 wa = *(const float4*)(w1 + (size_t)j * CIN + 8 * l);
        float4 wbv = *(const float4*)(w1 + (size_t)j * CIN + 8 * l + 4);
        const float4 pa = *(const float4*)(psm + 8 * l);
        const float4 pb = *(const float4*)(psm + 8 * l + 4);
        float s = wa.x * pa.x + wa.y * pa.y + wa.z * pa.z + wa.w * pa.w
                + wbv.x * pb.x + wbv.y * pb.y + wbv.z * pb.z + wbv.w * pb.w;
#pragma unroll
        for (int o = 16; o > 0; o >>= 1) s += __shfl_xor_sync(0xffffffffu, s, o);
        if (l == 0) hs[j] = fmaxf(s + b1[j], 0.f);
    }
    __syncthreads();

    // raw = w2 @ h + b2: warp per row, lane covers 4 k's (coalesced 512B/row)
#pragma unroll 2
    for (int i = 0; i < (COUT * NB) / 8; i++) {
        int row = w * ((COUT * NB) / 8) + i;
        float4 wv = *(const float4*)(w2 + (size_t)row * HID + 4 * l);
        const float4 hv = *(const float4*)(hs + 4 * l);
        float s = wv.x * hv.x + wv.y * hv.y + wv.z * hv.z + wv.w * hv.w;
#pragma unroll
        for (int o = 16; o > 0; o >>= 1) s += __shfl_xor_sync(0xffffffffu, s, o);
        if (l == 0) raw[row] = s + b2[row];
    }
    __syncthreads();

    // softmax over n for o = t
    float v[NB];
#pragma unroll
    for (int n = 0; n < NB; n++) v[n] = raw[t * NB + n];
    float m = v[0];
#pragma unroll
    for (int n = 1; n < NB; n++) m = fmaxf(m, v[n]);
    float e[NB], s = 0.f;
#pragma unroll
    for (int n = 0; n < NB; n++) { e[n] = expf(v[n] - m); s += e[n]; }
    float inv = 1.f / s;
#pragma unroll
    for (int n = 0; n < NB; n++) g_mix[b * COUT * NB + t * NB + n] = e[n] * inv;
}

// -------- kernel 4: out[b,o,p] = sum_n mix[b,o,n] * y[b,n,p] --------
__global__ __launch_bounds__(256)
void apply_kernel(float* __restrict__ out) {
    __shared__ __align__(16) float ms[128 * NB];
    const int b    = blockIdx.x >> 3;
    const int half = (blockIdx.x >> 2) & 1;
    const int t    = threadIdx.x;
    const int p0   = (blockIdx.x & 3) * 1024 + t * 4;

    for (int i = t; i < 128 * NB; i += 256)
        ms[i] = g_mix[b * COUT * NB + half * 128 * NB + i];
    __syncthreads();

    unsigned long long y2[NB][2];
#pragma unroll
    for (int n = 0; n < NB; n++) {
        float4 v = *(const float4*)(g_y + (size_t)(b * NB + n) * HWPIX + p0);
        y2[n][0] = pk2(v.x, v.y);
        y2[n][1] = pk2(v.z, v.w);
    }

    float* ob = out + ((size_t)b * COUT + half * 128) * HWPIX + p0;
    for (int o = 0; o < 128; o++) {
        const float4 m0 = *(const float4*)(ms + o * NB);
        const float4 m1 = *(const float4*)(ms + o * NB + 4);
        float mv[8] = {m0.x, m0.y, m0.z, m0.w, m1.x, m1.y, m1.z, m1.w};
        unsigned long long a0 = 0ULL, a1 = 0ULL;
#pragma unroll
        for (int n = 0; n < NB; n++) {
            unsigned long long fb = pk2(mv[n], mv[n]);
            a0 = fma2(y2[n][0], fb, a0);
            a1 = fma2(y2[n][1], fb, a1);
        }
        float o0, o1, o2, o3;
        upk2(a0, o0, o1);
        upk2(a1, o2, o3);
        __stcs((float4*)(ob + (size_t)o * HWPIX), make_float4(o0, o1, o2, o3));
    }
}

extern "C" void kernel_launch(void* const* d_in, const int* in_sizes, int n_in,
                              void* d_out, int out_size) {
    const float* x  = (const float*)d_in[0];
    const float* w1 = (const float*)d_in[1];
    const float* b1 = (const float*)d_in[2];
    const float* w2 = (const float*)d_in[3];
    const float* b2 = (const float*)d_in[4];
    const float* bf = (const float*)d_in[5];
    float* out = (float*)d_out;

    const int smem_bytes = (FS2_ELEMS + 2 * XT_ELEMS) * (int)sizeof(float2);  // ~55.9 KB
    cudaFuncSetAttribute(conv_pool_kernel,
                         cudaFuncAttributeMaxDynamicSharedMemorySize, smem_bytes);

    zero_kernel<<<(BB * CIN / 4 + 255) / 256, 256>>>();
    conv_pool_kernel<<<BB * 4, CONV_THREADS, smem_bytes>>>(x, bf);
    mlp_kernel<<<BB, 256>>>(w1, b1, w2, b2);
    apply_kernel<<<BB * 8, 256>>>(out);
}